// round 1
// baseline (speedup 1.0000x reference)
#include <cuda_runtime.h>
#include <math.h>

// Problem constants (fixed by the reference)
#define NN   4096
#define DD   1024
#define HH   16
#define HDD  64
#define NOFF 24

// Scratch (no cudaMalloc allowed -> __device__ globals)
__device__ float g_qkv[(size_t)NN * 3 * DD];    // [N, 3D]  q|k|v
__device__ float g_gate[(size_t)NN * DD];       // sigmoid(x@Wgate+bgate)
__device__ float g_gated[(size_t)NN * DD];      // attn_out * gate

__constant__ int c_off[NOFF] = {0,1,2,3,4,6,8,12,16,24,32,48,64,96,128,
                                192,256,384,512,768,1024,1536,2048,3072};

// ---------------------------------------------------------------------------
// fp32 SGEMM: C[M,N] = A[M,K] @ B[K,N] + bias[N], optional sigmoid epilogue.
// 128x128 tile, BK=16, 256 threads, 8x8 register micro-tile.
// M,N,K all multiples of tile dims here -> no bounds checks.
// ---------------------------------------------------------------------------
#define BM 128
#define BN 128
#define BK 16

template <int ACT>
__global__ void __launch_bounds__(256, 2)
sgemm_kernel(const float* __restrict__ A, const float* __restrict__ B,
             const float* __restrict__ bias, float* __restrict__ C,
             int M, int N, int K)
{
    __shared__ float As[BK][BM];   // transposed A tile
    __shared__ float Bs[BK][BN];

    const int tid = threadIdx.x;
    const int tx  = tid & 15;      // 0..15 -> 8 output cols each
    const int ty  = tid >> 4;      // 0..15 -> 8 output rows each
    const int row0 = blockIdx.y * BM;
    const int col0 = blockIdx.x * BN;

    const float* Aptr = A + (size_t)row0 * K;
    const float* Bptr = B + col0;

    float acc[8][8];
#pragma unroll
    for (int i = 0; i < 8; i++)
#pragma unroll
        for (int j = 0; j < 8; j++) acc[i][j] = 0.f;

    for (int k0 = 0; k0 < K; k0 += BK) {
        // Load A tile: 128 rows x 16 cols, float4 along K, store transposed.
#pragma unroll
        for (int i = 0; i < 2; i++) {
            int q  = tid + i * 256;          // 0..511 quads
            int ar = q >> 2;                 // 0..127
            int ak = (q & 3) << 2;           // 0,4,8,12
            float4 a = *(const float4*)(Aptr + (size_t)ar * K + k0 + ak);
            As[ak + 0][ar] = a.x;
            As[ak + 1][ar] = a.y;
            As[ak + 2][ar] = a.z;
            As[ak + 3][ar] = a.w;
        }
        // Load B tile: 16 rows x 128 cols, float4 along N (coalesced).
#pragma unroll
        for (int i = 0; i < 2; i++) {
            int q  = tid + i * 256;
            int br = q >> 5;                 // 0..15
            int bn = (q & 31) << 2;          // 0..124
            *(float4*)(&Bs[br][bn]) =
                *(const float4*)(Bptr + (size_t)(k0 + br) * N + bn);
        }
        __syncthreads();

#pragma unroll
        for (int kk = 0; kk < BK; kk++) {
            float a[8], b[8];
            *(float4*)(a)     = *(const float4*)(&As[kk][ty * 8]);
            *(float4*)(a + 4) = *(const float4*)(&As[kk][ty * 8 + 4]);
            *(float4*)(b)     = *(const float4*)(&Bs[kk][tx * 8]);
            *(float4*)(b + 4) = *(const float4*)(&Bs[kk][tx * 8 + 4]);
#pragma unroll
            for (int i = 0; i < 8; i++)
#pragma unroll
                for (int j = 0; j < 8; j++)
                    acc[i][j] += a[i] * b[j];
        }
        __syncthreads();
    }

    // Epilogue: bias (+ optional sigmoid), vectorized stores.
    const float* brow = bias + col0 + tx * 8;
#pragma unroll
    for (int i = 0; i < 8; i++) {
        float* crow = C + (size_t)(row0 + ty * 8 + i) * N + col0 + tx * 8;
#pragma unroll
        for (int j = 0; j < 8; j += 4) {
            float4 v;
            v.x = acc[i][j + 0] + brow[j + 0];
            v.y = acc[i][j + 1] + brow[j + 1];
            v.z = acc[i][j + 2] + brow[j + 2];
            v.w = acc[i][j + 3] + brow[j + 3];
            if (ACT == 1) {
                v.x = 1.f / (1.f + __expf(-v.x));
                v.y = 1.f / (1.f + __expf(-v.y));
                v.z = 1.f / (1.f + __expf(-v.z));
                v.w = 1.f / (1.f + __expf(-v.w));
            }
            *(float4*)(crow + j) = v;
        }
    }
}

// ---------------------------------------------------------------------------
// 24-tap dilated attention + gate multiply, one warp per (n, h).
// Each lane owns 2 head-dims (float2 at d = 2*lane).
// Invalid taps (n - delta < 0): q.k term is 0 (score = pos_bias only) and the
// v contribution is 0 — this matches the reference's zero-padded gather, where
// masked taps STILL participate in the softmax with score = pos_bias.
// ---------------------------------------------------------------------------
__global__ void attn_kernel(const float* __restrict__ qkv,
                            const float* __restrict__ gate,
                            const float* __restrict__ pos_bias,
                            float* __restrict__ gated)
{
    const int gw   = (blockIdx.x * blockDim.x + threadIdx.x) >> 5;
    const int lane = threadIdx.x & 31;
    const int n = gw >> 4;     // /H
    const int h = gw & 15;     // %H
    if (n >= NN) return;

    const float scale = 0.125f;   // 64^-0.5
    const size_t rowQ = (size_t)n * (3 * DD) + h * HDD;
    const float2 q = *(const float2*)(qkv + rowQ + 2 * lane);

    float sc[NOFF];
#pragma unroll
    for (int o = 0; o < NOFF; o++) {
        const int src = n - c_off[o];
        float s = 0.f;
        if (src >= 0) {
            const float2 k = *(const float2*)(qkv + (size_t)src * (3 * DD) + DD
                                              + h * HDD + 2 * lane);
            s = q.x * k.x + q.y * k.y;
        }
#pragma unroll
        for (int d = 16; d > 0; d >>= 1)
            s += __shfl_xor_sync(0xffffffffu, s, d);
        sc[o] = s * scale + pos_bias[o * HH + h];
    }

    float mx = sc[0];
#pragma unroll
    for (int o = 1; o < NOFF; o++) mx = fmaxf(mx, sc[o]);
    float den = 0.f;
#pragma unroll
    for (int o = 0; o < NOFF; o++) { sc[o] = expf(sc[o] - mx); den += sc[o]; }
    const float inv = 1.f / den;

    float ax = 0.f, ay = 0.f;
#pragma unroll
    for (int o = 0; o < NOFF; o++) {
        const int src = n - c_off[o];
        if (src >= 0) {
            const float2 v = *(const float2*)(qkv + (size_t)src * (3 * DD) + 2 * DD
                                              + h * HDD + 2 * lane);
            const float w = sc[o] * inv;
            ax += w * v.x;
            ay += w * v.y;
        }
    }

    const size_t oidx = (size_t)n * DD + h * HDD + 2 * lane;
    const float2 g = *(const float2*)(gate + oidx);
    float2 r;
    r.x = ax * g.x;
    r.y = ay * g.y;
    *(float2*)(gated + oidx) = r;
}

// ---------------------------------------------------------------------------
extern "C" void kernel_launch(void* const* d_in, const int* in_sizes, int n_in,
                              void* d_out, int out_size)
{
    const float* x     = (const float*)d_in[0];
    const float* Wqkv  = (const float*)d_in[1];
    const float* bqkv  = (const float*)d_in[2];
    const float* Wout  = (const float*)d_in[3];
    const float* bout  = (const float*)d_in[4];
    const float* Wgate = (const float*)d_in[5];
    const float* bgate = (const float*)d_in[6];
    const float* pbias = (const float*)d_in[7];
    float* out = (float*)d_out;

    float *qkv, *gate, *gated;
    cudaGetSymbolAddress((void**)&qkv,   g_qkv);
    cudaGetSymbolAddress((void**)&gate,  g_gate);
    cudaGetSymbolAddress((void**)&gated, g_gated);

    const dim3 blk(256);

    // 1) qkv = x @ Wqkv + bqkv            [4096, 3072]
    sgemm_kernel<0><<<dim3(3 * DD / BN, NN / BM), blk>>>(x, Wqkv, bqkv, qkv,
                                                         NN, 3 * DD, DD);
    // 2) gate = sigmoid(x @ Wgate + bgate) [4096, 1024]
    sgemm_kernel<1><<<dim3(DD / BN, NN / BM), blk>>>(x, Wgate, bgate, gate,
                                                     NN, DD, DD);
    // 3) attention + gate multiply -> gated [4096, 1024]
    const int total_threads = NN * HH * 32;
    attn_kernel<<<total_threads / 256, 256>>>(qkv, gate, pbias, gated);
    // 4) out = gated @ Wout + bout         [4096, 1024]
    sgemm_kernel<0><<<dim3(DD / BN, NN / BM), blk>>>(gated, Wout, bout, out,
                                                     NN, DD, DD);
}

// round 3
// speedup vs baseline: 1.6860x; 1.6860x over previous
#include <cuda_runtime.h>
#include <cuda_bf16.h>
#include <math.h>
#include <stdint.h>

// Problem constants
#define NN   4096
#define DD   1024
#define HH   16
#define HDD  64
#define NOFF 24
#define K2   3072           // split-K: [hi | lo | hi] x [hi | hi | lo]

// ---------------------------------------------------------------------------
// Scratch (__device__ globals; no cudaMalloc allowed)
// ---------------------------------------------------------------------------
__device__ __align__(16) __nv_bfloat16 g_xs   [(size_t)NN * K2];      // x split
__device__ __align__(16) __nv_bfloat16 g_gs   [(size_t)NN * K2];      // gated split
__device__ __align__(16) __nv_bfloat16 g_Wqkvt[(size_t)(3*DD) * K2];  // WqkvT split
__device__ __align__(16) __nv_bfloat16 g_Wgt  [(size_t)DD * K2];      // WgateT split
__device__ __align__(16) __nv_bfloat16 g_Wot  [(size_t)DD * K2];      // WoutT split
__device__ __align__(16) float g_qkv [(size_t)NN * 3 * DD];
__device__ __align__(16) float g_gate[(size_t)NN * DD];
__device__ __align__(16) float g_gated[(size_t)NN * DD];

__constant__ int c_off[NOFF] = {0,1,2,3,4,6,8,12,16,24,32,48,64,96,128,
                                192,256,384,512,768,1024,1536,2048,3072};

// ---------------------------------------------------------------------------
// PTX helpers (sm_80-level only: works at compute_103 family target)
// ---------------------------------------------------------------------------
__device__ __forceinline__ uint32_t smem_u32(const void* p) {
    uint32_t a;
    asm("{ .reg .u64 t; cvta.to.shared.u64 t, %1; cvt.u32.u64 %0, t; }"
        : "=r"(a) : "l"(p));
    return a;
}
__device__ __forceinline__ void cp16(uint32_t s, const void* g) {
    asm volatile("cp.async.cg.shared.global [%0], [%1], 16;" :: "r"(s), "l"(g));
}
#define CP_COMMIT()  asm volatile("cp.async.commit_group;" ::: "memory")
#define CP_WAIT(n)   asm volatile("cp.async.wait_group %0;" :: "n"(n) : "memory")

__device__ __forceinline__ void ldm4(uint32_t* r, uint32_t addr) {
    asm volatile("ldmatrix.sync.aligned.m8n8.x4.shared.b16 {%0,%1,%2,%3}, [%4];"
                 : "=r"(r[0]), "=r"(r[1]), "=r"(r[2]), "=r"(r[3]) : "r"(addr));
}
__device__ __forceinline__ void mma_bf16(float* d, const uint32_t* a, const uint32_t* b) {
    asm volatile(
        "mma.sync.aligned.m16n8k16.row.col.f32.bf16.bf16.f32 "
        "{%0,%1,%2,%3}, {%4,%5,%6,%7}, {%8,%9}, {%0,%1,%2,%3};"
        : "+f"(d[0]), "+f"(d[1]), "+f"(d[2]), "+f"(d[3])
        : "r"(a[0]), "r"(a[1]), "r"(a[2]), "r"(a[3]), "r"(b[0]), "r"(b[1]));
}

// ---------------------------------------------------------------------------
// Conversion kernels (split fp32 -> [hi | lo | hi] bf16 along K)
// ---------------------------------------------------------------------------
__global__ void conv_split_kernel(const float* __restrict__ X,
                                  __nv_bfloat16* __restrict__ Y, int total)
{
    int idx = blockIdx.x * blockDim.x + threadIdx.x;
    if (idx >= total) return;
    int m = idx >> 10, k = idx & 1023;
    float v = X[idx];
    __nv_bfloat16 hi = __float2bfloat16(v);
    __nv_bfloat16 lo = __float2bfloat16(v - __bfloat162float(hi));
    size_t b = (size_t)m * K2;
    Y[b + k] = hi;
    Y[b + 1024 + k] = lo;
    Y[b + 2048 + k] = hi;
}

// W [1024, Ncols] f32 -> Wt [Ncols, 3072] bf16 with blocks [hi | hi | lo]
__global__ void conv_w_kernel(const float* __restrict__ W,
                              __nv_bfloat16* __restrict__ Wt, int Ncols)
{
    __shared__ float t[32][33];
    const int tx = threadIdx.x, ty = threadIdx.y;
    const int n0 = blockIdx.x * 32, k0 = blockIdx.y * 32;
#pragma unroll
    for (int i = 0; i < 4; i++)
        t[ty + 8 * i][tx] = W[(size_t)(k0 + ty + 8 * i) * Ncols + n0 + tx];
    __syncthreads();
#pragma unroll
    for (int i = 0; i < 4; i++) {
        int n = n0 + ty + 8 * i;
        int k = k0 + tx;
        float v = t[tx][ty + 8 * i];
        __nv_bfloat16 hi = __float2bfloat16(v);
        __nv_bfloat16 lo = __float2bfloat16(v - __bfloat162float(hi));
        size_t b = (size_t)n * K2;
        Wt[b + k] = hi;
        Wt[b + 1024 + k] = hi;
        Wt[b + 2048 + k] = lo;
    }
}

// ---------------------------------------------------------------------------
// bf16 mma.sync GEMM: C[M, Ncols] = A'[M, 3072] @ Bt'[Ncols, 3072]^T + bias
// 128x128 tile, BK=32, 256 threads (4x2 warps, warp tile 32x64),
// 4-stage cp.async pipeline, padded 80B smem rows (conflict-free ldmatrix).
// ---------------------------------------------------------------------------
#define GBM     128
#define GBN     128
#define GBK     32
#define NKC     (K2 / GBK)          // 96
#define ROW_B   80                  // 32 bf16 (64B) + 16B pad
#define A_BYTES (GBM * ROW_B)       // 10240
#define STAGE_B (2 * A_BYTES)       // 20480 (A tile + B tile)
#define STAGES  4
#define SMEM_BYTES (STAGES * STAGE_B)   // 81920

__device__ __forceinline__ void issue_stage(const char* Ab, const char* Bb,
                                            uint32_t sbase, int kc, int s, int tid)
{
    const size_t rs = (size_t)K2 * 2;
    const char* Ak = Ab + (size_t)kc * (GBK * 2);
    const char* Bk = Bb + (size_t)kc * (GBK * 2);
    const uint32_t sA = sbase + s * STAGE_B;
    const uint32_t sB = sA + A_BYTES;
    const int r  = tid >> 1;
    const int co = (tid & 1) * 32;
    cp16(sA + r * ROW_B + co,      Ak + (size_t)r * rs + co);
    cp16(sA + r * ROW_B + co + 16, Ak + (size_t)r * rs + co + 16);
    cp16(sB + r * ROW_B + co,      Bk + (size_t)r * rs + co);
    cp16(sB + r * ROW_B + co + 16, Bk + (size_t)r * rs + co + 16);
    CP_COMMIT();
}

template <int ACT>
__global__ void __launch_bounds__(256, 2)
gemm_mma(const __nv_bfloat16* __restrict__ A,   // [M, 3072] row-major
         const __nv_bfloat16* __restrict__ Bt,  // [Ncols, 3072] row-major
         const float* __restrict__ bias,
         float* __restrict__ C, int Ncols)
{
    extern __shared__ char smem[];
    const int tid = threadIdx.x, lane = tid & 31, wid = tid >> 5;
    const int wm = wid & 3;        // 0..3 -> M offset wm*32
    const int wn = wid >> 2;       // 0..1 -> N offset wn*64
    const int m0 = blockIdx.y * GBM;
    const int n0 = blockIdx.x * GBN;
    const uint32_t sb = smem_u32(smem);

    const char* Ab = (const char*)A + (size_t)m0 * K2 * 2;
    const char* Bb = (const char*)Bt + (size_t)n0 * K2 * 2;

    float acc[2][8][4];
#pragma unroll
    for (int i = 0; i < 2; i++)
#pragma unroll
        for (int j = 0; j < 8; j++)
#pragma unroll
            for (int q = 0; q < 4; q++) acc[i][j][q] = 0.f;

    issue_stage(Ab, Bb, sb, 0, 0, tid);
    issue_stage(Ab, Bb, sb, 1, 1, tid);
    issue_stage(Ab, Bb, sb, 2, 2, tid);

    // ldmatrix lane addressing (within stage buffer):
    // A (m-major rows): lanes 0-15 rows m0..15 @k0, lanes 16-31 same rows @+16B
    const uint32_t aoff = (uint32_t)((wm * 32 + (lane & 15)) * ROW_B
                                     + (lane >> 4) * 16);
    // B (n-major rows): r0/r1 = n-tile0 (k0-7 / k8-15), r2/r3 = n-tile1
    const uint32_t boff = (uint32_t)A_BYTES
                        + (uint32_t)((wn * 64 + ((lane >> 4) & 1) * 8 + (lane & 7)) * ROW_B
                                     + ((lane >> 3) & 1) * 16);

    for (int kc = 0; kc < NKC; kc++) {
        CP_WAIT(2);                 // stage kc resident (3+kc groups committed)
        __syncthreads();            // all warps done with buffer (kc-1)%4
        if (kc + 3 < NKC) issue_stage(Ab, Bb, sb, kc + 3, (kc + 3) & 3, tid);
        else              CP_COMMIT();   // keep group count aligned

        const uint32_t sA = sb + (kc & 3) * STAGE_B;
#pragma unroll
        for (int kp = 0; kp < 2; kp++) {
            uint32_t af[2][4], bf[4][4];
            ldm4(af[0], sA + aoff + kp * 32);
            ldm4(af[1], sA + aoff + 16 * ROW_B + kp * 32);
#pragma unroll
            for (int j = 0; j < 4; j++)
                ldm4(bf[j], sA + boff + j * 16 * ROW_B + kp * 32);
#pragma unroll
            for (int mi = 0; mi < 2; mi++)
#pragma unroll
                for (int nj = 0; nj < 8; nj++)
                    mma_bf16(acc[mi][nj], af[mi], &bf[nj >> 1][(nj & 1) * 2]);
        }
    }

    // Epilogue: thread (gid, tig) owns C[m.. , n..] pairs per fragment layout.
    const int gid = lane >> 2, tig = lane & 3;
#pragma unroll
    for (int mi = 0; mi < 2; mi++) {
        const int r0 = m0 + wm * 32 + mi * 16 + gid;
#pragma unroll
        for (int nj = 0; nj < 8; nj++) {
            const int col = n0 + wn * 64 + nj * 8 + tig * 2;
            const float b0 = bias[col], b1 = bias[col + 1];
            float2 v;
            v.x = acc[mi][nj][0] + b0;
            v.y = acc[mi][nj][1] + b1;
            if (ACT == 1) {
                v.x = 1.f / (1.f + __expf(-v.x));
                v.y = 1.f / (1.f + __expf(-v.y));
            }
            *(float2*)(C + (size_t)r0 * Ncols + col) = v;
            v.x = acc[mi][nj][2] + b0;
            v.y = acc[mi][nj][3] + b1;
            if (ACT == 1) {
                v.x = 1.f / (1.f + __expf(-v.x));
                v.y = 1.f / (1.f + __expf(-v.y));
            }
            *(float2*)(C + (size_t)(r0 + 8) * Ncols + col) = v;
        }
    }
}

// ---------------------------------------------------------------------------
// 24-tap dilated attention + gate multiply, one warp per (n, h).
// ---------------------------------------------------------------------------
__global__ void attn_kernel(const float* __restrict__ qkv,
                            const float* __restrict__ gate,
                            const float* __restrict__ pos_bias,
                            float* __restrict__ gated)
{
    const int gw   = (blockIdx.x * blockDim.x + threadIdx.x) >> 5;
    const int lane = threadIdx.x & 31;
    const int n = gw >> 4;
    const int h = gw & 15;
    if (n >= NN) return;

    const float scale = 0.125f;
    const size_t rowQ = (size_t)n * (3 * DD) + h * HDD;
    const float2 q = *(const float2*)(qkv + rowQ + 2 * lane);

    float sc[NOFF];
#pragma unroll
    for (int o = 0; o < NOFF; o++) {
        const int src = n - c_off[o];
        float s = 0.f;
        if (src >= 0) {
            const float2 k = *(const float2*)(qkv + (size_t)src * (3 * DD) + DD
                                              + h * HDD + 2 * lane);
            s = q.x * k.x + q.y * k.y;
        }
#pragma unroll
        for (int d = 16; d > 0; d >>= 1)
            s += __shfl_xor_sync(0xffffffffu, s, d);
        sc[o] = s * scale + pos_bias[o * HH + h];
    }

    float mx = sc[0];
#pragma unroll
    for (int o = 1; o < NOFF; o++) mx = fmaxf(mx, sc[o]);
    float den = 0.f;
#pragma unroll
    for (int o = 0; o < NOFF; o++) { sc[o] = expf(sc[o] - mx); den += sc[o]; }
    const float inv = 1.f / den;

    float ax = 0.f, ay = 0.f;
#pragma unroll
    for (int o = 0; o < NOFF; o++) {
        const int src = n - c_off[o];
        if (src >= 0) {
            const float2 v = *(const float2*)(qkv + (size_t)src * (3 * DD) + 2 * DD
                                              + h * HDD + 2 * lane);
            const float w = sc[o] * inv;
            ax += w * v.x;
            ay += w * v.y;
        }
    }

    const size_t oidx = (size_t)n * DD + h * HDD + 2 * lane;
    const float2 g = *(const float2*)(gate + oidx);
    float2 r;
    r.x = ax * g.x;
    r.y = ay * g.y;
    *(float2*)(gated + oidx) = r;
}

// ---------------------------------------------------------------------------
extern "C" void kernel_launch(void* const* d_in, const int* in_sizes, int n_in,
                              void* d_out, int out_size)
{
    const float* x     = (const float*)d_in[0];
    const float* Wqkv  = (const float*)d_in[1];
    const float* bqkv  = (const float*)d_in[2];
    const float* Wout  = (const float*)d_in[3];
    const float* bout  = (const float*)d_in[4];
    const float* Wgate = (const float*)d_in[5];
    const float* bgate = (const float*)d_in[6];
    const float* pbias = (const float*)d_in[7];
    float* out = (float*)d_out;

    __nv_bfloat16 *xs, *gs, *Wqkvt, *Wgt, *Wot;
    float *qkv, *gate, *gated;
    cudaGetSymbolAddress((void**)&xs,    g_xs);
    cudaGetSymbolAddress((void**)&gs,    g_gs);
    cudaGetSymbolAddress((void**)&Wqkvt, g_Wqkvt);
    cudaGetSymbolAddress((void**)&Wgt,   g_Wgt);
    cudaGetSymbolAddress((void**)&Wot,   g_Wot);
    cudaGetSymbolAddress((void**)&qkv,   g_qkv);
    cudaGetSymbolAddress((void**)&gate,  g_gate);
    cudaGetSymbolAddress((void**)&gated, g_gated);

    cudaFuncSetAttribute(gemm_mma<0>, cudaFuncAttributeMaxDynamicSharedMemorySize, SMEM_BYTES);
    cudaFuncSetAttribute(gemm_mma<1>, cudaFuncAttributeMaxDynamicSharedMemorySize, SMEM_BYTES);

    // Conversions
    conv_split_kernel<<<(NN * DD) / 256, 256>>>(x, xs, NN * DD);
    conv_w_kernel<<<dim3(3 * DD / 32, DD / 32), dim3(32, 8)>>>(Wqkv, Wqkvt, 3 * DD);
    conv_w_kernel<<<dim3(DD / 32, DD / 32), dim3(32, 8)>>>(Wgate, Wgt, DD);
    conv_w_kernel<<<dim3(DD / 32, DD / 32), dim3(32, 8)>>>(Wout, Wot, DD);

    // 1) qkv = x @ Wqkv + bqkv
    gemm_mma<0><<<dim3(3 * DD / GBN, NN / GBM), 256, SMEM_BYTES>>>(xs, Wqkvt, bqkv, qkv, 3 * DD);
    // 2) gate = sigmoid(x @ Wgate + bgate)
    gemm_mma<1><<<dim3(DD / GBN, NN / GBM), 256, SMEM_BYTES>>>(xs, Wgt, bgate, gate, DD);
    // 3) attention + gate multiply
    attn_kernel<<<(NN * HH * 32) / 256, 256>>>(qkv, gate, pbias, gated);
    // 4) out = gated @ Wout + bout
    conv_split_kernel<<<(NN * DD) / 256, 256>>>(gated, gs, NN * DD);
    gemm_mma<0><<<dim3(DD / GBN, NN / GBM), 256, SMEM_BYTES>>>(gs, Wot, bout, out, DD);
}

// round 4
// speedup vs baseline: 1.7758x; 1.0533x over previous
#include <cuda_runtime.h>
#include <cuda_bf16.h>
#include <math.h>
#include <stdint.h>

// Problem constants
#define NN   4096
#define DD   1024
#define HH   16
#define HDD  64
#define NOFF 24
#define K2   3072           // split-K: [hi | lo | hi] x [hi | hi | lo]

// ---------------------------------------------------------------------------
// Scratch (__device__ globals; no cudaMalloc allowed)
// ---------------------------------------------------------------------------
__device__ __align__(16) __nv_bfloat16 g_xs  [(size_t)NN * K2];        // x split
__device__ __align__(16) __nv_bfloat16 g_gs  [(size_t)NN * K2];        // gated split
__device__ __align__(16) __nv_bfloat16 g_W1t [(size_t)(4*DD) * K2];    // [WqkvT ; WgateT] split
__device__ __align__(16) __nv_bfloat16 g_Wot [(size_t)DD * K2];        // WoutT split
__device__ __align__(16) float g_qkv [(size_t)NN * 3 * DD];
__device__ __align__(16) float g_gate[(size_t)NN * DD];

__constant__ int c_off[NOFF] = {0,1,2,3,4,6,8,12,16,24,32,48,64,96,128,
                                192,256,384,512,768,1024,1536,2048,3072};

// ---------------------------------------------------------------------------
// PTX helpers (sm_80-level only: compute_103 family target accepts these)
// ---------------------------------------------------------------------------
__device__ __forceinline__ uint32_t smem_u32(const void* p) {
    uint32_t a;
    asm("{ .reg .u64 t; cvta.to.shared.u64 t, %1; cvt.u32.u64 %0, t; }"
        : "=r"(a) : "l"(p));
    return a;
}
__device__ __forceinline__ void cp16(uint32_t s, const void* g) {
    asm volatile("cp.async.cg.shared.global [%0], [%1], 16;" :: "r"(s), "l"(g));
}
#define CP_COMMIT()  asm volatile("cp.async.commit_group;" ::: "memory")
#define CP_WAIT(n)   asm volatile("cp.async.wait_group %0;" :: "n"(n) : "memory")

__device__ __forceinline__ void ldm4(uint32_t* r, uint32_t addr) {
    asm volatile("ldmatrix.sync.aligned.m8n8.x4.shared.b16 {%0,%1,%2,%3}, [%4];"
                 : "=r"(r[0]), "=r"(r[1]), "=r"(r[2]), "=r"(r[3]) : "r"(addr));
}
__device__ __forceinline__ void mma_bf16(float* d, const uint32_t* a, const uint32_t* b) {
    asm volatile(
        "mma.sync.aligned.m16n8k16.row.col.f32.bf16.bf16.f32 "
        "{%0,%1,%2,%3}, {%4,%5,%6,%7}, {%8,%9}, {%0,%1,%2,%3};"
        : "+f"(d[0]), "+f"(d[1]), "+f"(d[2]), "+f"(d[3])
        : "r"(a[0]), "r"(a[1]), "r"(a[2]), "r"(a[3]), "r"(b[0]), "r"(b[1]));
}

// ---------------------------------------------------------------------------
// Conversions
// ---------------------------------------------------------------------------
__global__ void conv_split_kernel(const float* __restrict__ X,
                                  __nv_bfloat16* __restrict__ Y, int total)
{
    int idx = blockIdx.x * blockDim.x + threadIdx.x;
    if (idx >= total) return;
    int m = idx >> 10, k = idx & 1023;
    float v = X[idx];
    __nv_bfloat16 hi = __float2bfloat16(v);
    __nv_bfloat16 lo = __float2bfloat16(v - __bfloat162float(hi));
    size_t b = (size_t)m * K2;
    Y[b + k] = hi;
    Y[b + 1024 + k] = lo;
    Y[b + 2048 + k] = hi;
}

// W [1024, Ncols] f32 -> Wt rows [row_off + n], blocks [hi | hi | lo]
__global__ void conv_w_kernel(const float* __restrict__ W,
                              __nv_bfloat16* __restrict__ Wt, int Ncols, int row_off)
{
    __shared__ float t[32][33];
    const int tx = threadIdx.x, ty = threadIdx.y;
    const int n0 = blockIdx.x * 32, k0 = blockIdx.y * 32;
#pragma unroll
    for (int i = 0; i < 4; i++)
        t[ty + 8 * i][tx] = W[(size_t)(k0 + ty + 8 * i) * Ncols + n0 + tx];
    __syncthreads();
#pragma unroll
    for (int i = 0; i < 4; i++) {
        int n = n0 + ty + 8 * i;
        int k = k0 + tx;
        float v = t[tx][ty + 8 * i];
        __nv_bfloat16 hi = __float2bfloat16(v);
        __nv_bfloat16 lo = __float2bfloat16(v - __bfloat162float(hi));
        size_t b = (size_t)(row_off + n) * K2;
        Wt[b + k] = hi;
        Wt[b + 1024 + k] = hi;
        Wt[b + 2048 + k] = lo;
    }
}

// ---------------------------------------------------------------------------
// bf16 mma.sync GEMM: C = A'[M,3072] @ Bt'[Nc,3072]^T + bias
// CTA tile 128x256, BK=32, 256 threads (2x4 warps, warp tile 64x64),
// 4-stage cp.async pipeline, padded 80B smem rows (conflict-free ldmatrix).
// SPLIT mode: output columns >= 3072 go to C1 (stride 1024) with sigmoid+bias1.
// ---------------------------------------------------------------------------
#define GBM     128
#define GBN     256
#define GBK     32
#define NKC     (K2 / GBK)            // 96
#define ROW_B   80                    // 32 bf16 (64B) + 16B pad
#define A_BYTES (GBM * ROW_B)         // 10240
#define STAGE_B (A_BYTES + GBN * ROW_B)   // 30720
#define STAGES  4
#define SMEM_BYTES (STAGES * STAGE_B)     // 122880

__device__ __forceinline__ void issue_stage(const char* Ab, const char* Bb,
                                            uint32_t sbase, int kc, int s, int tid)
{
    const size_t rs = (size_t)K2 * 2;
    const char* Ak = Ab + (size_t)kc * (GBK * 2);
    const char* Bk = Bb + (size_t)kc * (GBK * 2);
    const uint32_t sA = sbase + s * STAGE_B;
    const uint32_t sB = sA + A_BYTES;
#pragma unroll
    for (int i = 0; i < 6; i++) {           // 1536 16B chunks / 256 threads
        int idx = tid + i * 256;
        int row = idx >> 2;
        int co  = (idx & 3) << 4;
        if (row < GBM)
            cp16(sA + row * ROW_B + co, Ak + (size_t)row * rs + co);
        else
            cp16(sB + (row - GBM) * ROW_B + co, Bk + (size_t)(row - GBM) * rs + co);
    }
    CP_COMMIT();
}

template <int SPLIT, int ACT>
__global__ void __launch_bounds__(256)
gemm_mma(const __nv_bfloat16* __restrict__ A,   // [M, 3072]
         const __nv_bfloat16* __restrict__ Bt,  // [Ncols, 3072]
         const float* __restrict__ bias0,
         const float* __restrict__ bias1,
         float* __restrict__ C0, float* __restrict__ C1)
{
    extern __shared__ char smem[];
    const int tid = threadIdx.x, lane = tid & 31, wid = tid >> 5;
    const int wm = wid & 1;        // 0..1 -> M offset wm*64
    const int wn = wid >> 1;       // 0..3 -> N offset wn*64
    const int m0 = blockIdx.y * GBM;
    const int n0 = blockIdx.x * GBN;
    const uint32_t sb = smem_u32(smem);

    const char* Ab = (const char*)A + (size_t)m0 * K2 * 2;
    const char* Bb = (const char*)Bt + (size_t)n0 * K2 * 2;

    float acc[4][8][4];
#pragma unroll
    for (int i = 0; i < 4; i++)
#pragma unroll
        for (int j = 0; j < 8; j++)
#pragma unroll
            for (int q = 0; q < 4; q++) acc[i][j][q] = 0.f;

    issue_stage(Ab, Bb, sb, 0, 0, tid);
    issue_stage(Ab, Bb, sb, 1, 1, tid);
    issue_stage(Ab, Bb, sb, 2, 2, tid);

    // ldmatrix lane addressing within a stage buffer
    const uint32_t aoff = (uint32_t)((wm * 64 + (lane & 15)) * ROW_B
                                     + (lane >> 4) * 16);
    const uint32_t boff = (uint32_t)A_BYTES
                        + (uint32_t)((wn * 64 + ((lane >> 4) & 1) * 8 + (lane & 7)) * ROW_B
                                     + ((lane >> 3) & 1) * 16);

    for (int kc = 0; kc < NKC; kc++) {
        CP_WAIT(2);
        __syncthreads();
        if (kc + 3 < NKC) issue_stage(Ab, Bb, sb, kc + 3, (kc + 3) & 3, tid);
        else              CP_COMMIT();

        const uint32_t sA = sb + (kc & 3) * STAGE_B;
#pragma unroll
        for (int kp = 0; kp < 2; kp++) {
            uint32_t af[4][4], bf[4][4];
#pragma unroll
            for (int mi = 0; mi < 4; mi++)
                ldm4(af[mi], sA + aoff + mi * 16 * ROW_B + kp * 32);
#pragma unroll
            for (int j = 0; j < 4; j++)
                ldm4(bf[j], sA + boff + j * 16 * ROW_B + kp * 32);
#pragma unroll
            for (int mi = 0; mi < 4; mi++)
#pragma unroll
                for (int nj = 0; nj < 8; nj++)
                    mma_bf16(acc[mi][nj], af[mi], &bf[nj >> 1][(nj & 1) * 2]);
        }
    }

    // Epilogue
    const int gid = lane >> 2, tig = lane & 3;
    float* C = C0;
    const float* bias = bias0;
    int stride = SPLIT ? (3 * DD) : DD;
    int ncol = n0;
    bool sig = (ACT == 1);
    if (SPLIT) {
        if (n0 >= 3 * DD) {           // gate region
            C = C1; bias = bias1; stride = DD; ncol = n0 - 3 * DD; sig = true;
        }
    }
#pragma unroll
    for (int mi = 0; mi < 4; mi++) {
        const int r0 = m0 + wm * 64 + mi * 16 + gid;
#pragma unroll
        for (int nj = 0; nj < 8; nj++) {
            const int col = ncol + wn * 64 + nj * 8 + tig * 2;
            const float b0 = bias[col], b1 = bias[col + 1];
            float2 v;
            v.x = acc[mi][nj][0] + b0;
            v.y = acc[mi][nj][1] + b1;
            if (sig) {
                v.x = 1.f / (1.f + __expf(-v.x));
                v.y = 1.f / (1.f + __expf(-v.y));
            }
            *(float2*)(C + (size_t)r0 * stride + col) = v;
            v.x = acc[mi][nj][2] + b0;
            v.y = acc[mi][nj][3] + b1;
            if (sig) {
                v.x = 1.f / (1.f + __expf(-v.x));
                v.y = 1.f / (1.f + __expf(-v.y));
            }
            *(float2*)(C + (size_t)(r0 + 8) * stride + col) = v;
        }
    }
}

// ---------------------------------------------------------------------------
// 24-tap dilated attention + gate multiply; writes split-bf16 gs directly.
// One warp per (n, h); each lane owns dims 2*lane, 2*lane+1.
// ---------------------------------------------------------------------------
__global__ void attn_kernel(const float* __restrict__ qkv,
                            const float* __restrict__ gate,
                            const float* __restrict__ pos_bias,
                            __nv_bfloat16* __restrict__ gs)
{
    const int gw   = (blockIdx.x * blockDim.x + threadIdx.x) >> 5;
    const int lane = threadIdx.x & 31;
    const int n = gw >> 4;
    const int h = gw & 15;
    if (n >= NN) return;

    const float scale = 0.125f;
    const size_t rowQ = (size_t)n * (3 * DD) + h * HDD;
    const float2 q = *(const float2*)(qkv + rowQ + 2 * lane);

    float sc[NOFF];
#pragma unroll
    for (int o = 0; o < NOFF; o++) {
        const int src = n - c_off[o];
        float s = 0.f;
        if (src >= 0) {
            const float2 k = *(const float2*)(qkv + (size_t)src * (3 * DD) + DD
                                              + h * HDD + 2 * lane);
            s = q.x * k.x + q.y * k.y;
        }
#pragma unroll
        for (int d = 16; d > 0; d >>= 1)
            s += __shfl_xor_sync(0xffffffffu, s, d);
        sc[o] = s * scale + pos_bias[o * HH + h];
    }

    float mx = sc[0];
#pragma unroll
    for (int o = 1; o < NOFF; o++) mx = fmaxf(mx, sc[o]);
    float den = 0.f;
#pragma unroll
    for (int o = 0; o < NOFF; o++) { sc[o] = __expf(sc[o] - mx); den += sc[o]; }
    const float inv = 1.f / den;

    float ax = 0.f, ay = 0.f;
#pragma unroll
    for (int o = 0; o < NOFF; o++) {
        const int src = n - c_off[o];
        if (src >= 0) {
            const float2 v = *(const float2*)(qkv + (size_t)src * (3 * DD) + 2 * DD
                                              + h * HDD + 2 * lane);
            const float w = sc[o] * inv;
            ax += w * v.x;
            ay += w * v.y;
        }
    }

    const int kcol = h * HDD + 2 * lane;
    const size_t oidx = (size_t)n * DD + kcol;
    const float2 g = *(const float2*)(gate + oidx);
    const float v0 = ax * g.x;
    const float v1 = ay * g.y;

    // split write: [hi | lo | hi]
    __nv_bfloat16 h0 = __float2bfloat16(v0);
    __nv_bfloat16 h1 = __float2bfloat16(v1);
    __nv_bfloat16 l0 = __float2bfloat16(v0 - __bfloat162float(h0));
    __nv_bfloat16 l1 = __float2bfloat16(v1 - __bfloat162float(h1));
    const size_t b = (size_t)n * K2 + kcol;
    __nv_bfloat162 hp; hp.x = h0; hp.y = h1;
    __nv_bfloat162 lp; lp.x = l0; lp.y = l1;
    *(__nv_bfloat162*)(gs + b)        = hp;
    *(__nv_bfloat162*)(gs + b + 1024) = lp;
    *(__nv_bfloat162*)(gs + b + 2048) = hp;
}

// ---------------------------------------------------------------------------
extern "C" void kernel_launch(void* const* d_in, const int* in_sizes, int n_in,
                              void* d_out, int out_size)
{
    const float* x     = (const float*)d_in[0];
    const float* Wqkv  = (const float*)d_in[1];
    const float* bqkv  = (const float*)d_in[2];
    const float* Wout  = (const float*)d_in[3];
    const float* bout  = (const float*)d_in[4];
    const float* Wgate = (const float*)d_in[5];
    const float* bgate = (const float*)d_in[6];
    const float* pbias = (const float*)d_in[7];
    float* out = (float*)d_out;

    __nv_bfloat16 *xs, *gs, *W1t, *Wot;
    float *qkv, *gate;
    cudaGetSymbolAddress((void**)&xs,   g_xs);
    cudaGetSymbolAddress((void**)&gs,   g_gs);
    cudaGetSymbolAddress((void**)&W1t,  g_W1t);
    cudaGetSymbolAddress((void**)&Wot,  g_Wot);
    cudaGetSymbolAddress((void**)&qkv,  g_qkv);
    cudaGetSymbolAddress((void**)&gate, g_gate);

    cudaFuncSetAttribute(gemm_mma<1,0>, cudaFuncAttributeMaxDynamicSharedMemorySize, SMEM_BYTES);
    cudaFuncSetAttribute(gemm_mma<0,0>, cudaFuncAttributeMaxDynamicSharedMemorySize, SMEM_BYTES);

    // Conversions
    conv_split_kernel<<<(NN * DD) / 256, 256>>>(x, xs, NN * DD);
    conv_w_kernel<<<dim3(3 * DD / 32, DD / 32), dim3(32, 8)>>>(Wqkv, W1t, 3 * DD, 0);
    conv_w_kernel<<<dim3(DD / 32, DD / 32), dim3(32, 8)>>>(Wgate, W1t, DD, 3 * DD);
    conv_w_kernel<<<dim3(DD / 32, DD / 32), dim3(32, 8)>>>(Wout, Wot, DD, 0);

    // 1) fused: [qkv | gate] = x @ [Wqkv | Wgate] (+sigmoid on gate region)
    gemm_mma<1,0><<<dim3(4 * DD / GBN, NN / GBM), 256, SMEM_BYTES>>>(
        xs, W1t, bqkv, bgate, qkv, gate);
    // 2) attention + gate multiply -> gs (split bf16)
    attn_kernel<<<(NN * HH * 32) / 256, 256>>>(qkv, gate, pbias, gs);
    // 3) out = gated @ Wout + bout
    gemm_mma<0,0><<<dim3(DD / GBN, NN / GBM), 256, SMEM_BYTES>>>(
        gs, Wot, bout, bout, out, out);
}

// round 5
// speedup vs baseline: 2.2433x; 1.2633x over previous
#include <cuda_runtime.h>
#include <cuda_fp16.h>
#include <math.h>
#include <stdint.h>

// Problem constants
#define NN   4096
#define DD   1024
#define HH   16
#define HDD  64
#define NOFF 24
#define KA   2048           // GEMM1 split-K: [Ah | Al] x [Bh | Bh]  (err ~2^-11)
#define KB   3072           // GEMM3 split-K: [Ah | Al | Ah] x [Bh | Bh | Bl] (err ~2^-22)

// ---------------------------------------------------------------------------
// Scratch (__device__ globals; no cudaMalloc allowed)
// ---------------------------------------------------------------------------
__device__ __align__(16) __half g_xs  [(size_t)NN * KA];        // x split (2-term)
__device__ __align__(16) __half g_gs  [(size_t)NN * KB];        // gated split (3-term)
__device__ __align__(16) __half g_W1t [(size_t)(4*DD) * KA];    // [WqkvT ; WgateT] (hi|hi)
__device__ __align__(16) __half g_Wot [(size_t)DD * KB];        // WoutT (hi|hi|lo)
__device__ __align__(16) float g_qkv [(size_t)NN * 3 * DD];
__device__ __align__(16) float g_gate[(size_t)NN * DD];

__constant__ int c_off[NOFF] = {0,1,2,3,4,6,8,12,16,24,32,48,64,96,128,
                                192,256,384,512,768,1024,1536,2048,3072};

// ---------------------------------------------------------------------------
// PTX helpers (sm_80-level only: compute_103 family target accepts these)
// ---------------------------------------------------------------------------
__device__ __forceinline__ uint32_t smem_u32(const void* p) {
    uint32_t a;
    asm("{ .reg .u64 t; cvta.to.shared.u64 t, %1; cvt.u32.u64 %0, t; }"
        : "=r"(a) : "l"(p));
    return a;
}
__device__ __forceinline__ void cp16(uint32_t s, const void* g) {
    asm volatile("cp.async.cg.shared.global [%0], [%1], 16;" :: "r"(s), "l"(g));
}
#define CP_COMMIT()  asm volatile("cp.async.commit_group;" ::: "memory")
#define CP_WAIT(n)   asm volatile("cp.async.wait_group %0;" :: "n"(n) : "memory")

__device__ __forceinline__ void ldm4(uint32_t* r, uint32_t addr) {
    asm volatile("ldmatrix.sync.aligned.m8n8.x4.shared.b16 {%0,%1,%2,%3}, [%4];"
                 : "=r"(r[0]), "=r"(r[1]), "=r"(r[2]), "=r"(r[3]) : "r"(addr));
}
__device__ __forceinline__ void mma_f16(float* d, const uint32_t* a, const uint32_t* b) {
    asm volatile(
        "mma.sync.aligned.m16n8k16.row.col.f32.f16.f16.f32 "
        "{%0,%1,%2,%3}, {%4,%5,%6,%7}, {%8,%9}, {%0,%1,%2,%3};"
        : "+f"(d[0]), "+f"(d[1]), "+f"(d[2]), "+f"(d[3])
        : "r"(a[0]), "r"(a[1]), "r"(a[2]), "r"(a[3]), "r"(b[0]), "r"(b[1]));
}

// ---------------------------------------------------------------------------
// Conversions
// ---------------------------------------------------------------------------
// x [4096,1024] f32 -> [hi | lo] fp16, row stride 2048
__global__ void conv_x_kernel(const float* __restrict__ X, __half* __restrict__ Y)
{
    int idx = blockIdx.x * blockDim.x + threadIdx.x;
    int m = idx >> 10, k = idx & 1023;
    float v = X[idx];
    __half hi = __float2half_rn(v);
    __half lo = __float2half_rn(v - __half2float(hi));
    size_t b = (size_t)m * KA;
    Y[b + k] = hi;
    Y[b + 1024 + k] = lo;
}

// W [1024, Ncols] f32 -> Wt rows [row_off + n] x 2048, blocks [hi | hi]
__global__ void conv_w2_kernel(const float* __restrict__ W,
                               __half* __restrict__ Wt, int Ncols, int row_off)
{
    __shared__ float t[32][33];
    const int tx = threadIdx.x, ty = threadIdx.y;
    const int n0 = blockIdx.x * 32, k0 = blockIdx.y * 32;
#pragma unroll
    for (int i = 0; i < 4; i++)
        t[ty + 8 * i][tx] = W[(size_t)(k0 + ty + 8 * i) * Ncols + n0 + tx];
    __syncthreads();
#pragma unroll
    for (int i = 0; i < 4; i++) {
        int n = n0 + ty + 8 * i;
        int k = k0 + tx;
        __half hi = __float2half_rn(t[tx][ty + 8 * i]);
        size_t b = (size_t)(row_off + n) * KA;
        Wt[b + k] = hi;
        Wt[b + 1024 + k] = hi;
    }
}

// Wout [1024, 1024] f32 -> Wt [n, 3072], blocks [hi | hi | lo]
__global__ void conv_w3_kernel(const float* __restrict__ W, __half* __restrict__ Wt)
{
    __shared__ float t[32][33];
    const int tx = threadIdx.x, ty = threadIdx.y;
    const int n0 = blockIdx.x * 32, k0 = blockIdx.y * 32;
#pragma unroll
    for (int i = 0; i < 4; i++)
        t[ty + 8 * i][tx] = W[(size_t)(k0 + ty + 8 * i) * DD + n0 + tx];
    __syncthreads();
#pragma unroll
    for (int i = 0; i < 4; i++) {
        int n = n0 + ty + 8 * i;
        int k = k0 + tx;
        float v = t[tx][ty + 8 * i];
        __half hi = __float2half_rn(v);
        __half lo = __float2half_rn(v - __half2float(hi));
        size_t b = (size_t)n * KB;
        Wt[b + k] = hi;
        Wt[b + 1024 + k] = hi;
        Wt[b + 2048 + k] = lo;
    }
}

// ---------------------------------------------------------------------------
// fp16 mma.sync GEMM: C = A'[M,KEL] @ Bt'[Nc,KEL]^T + bias
// CTA tile 128x256, BK=32, 256 threads (2x4 warps, warp tile 64x64),
// 4-stage cp.async pipeline, padded 80B smem rows (conflict-free ldmatrix).
// SPLIT mode: output columns >= 3072 go to C1 (stride 1024) with sigmoid+bias1.
// ---------------------------------------------------------------------------
#define GBM     128
#define GBN     256
#define GBK     32
#define ROW_B   80                    // 32 fp16 (64B) + 16B pad
#define A_BYTES (GBM * ROW_B)         // 10240
#define STAGE_B (A_BYTES + GBN * ROW_B)   // 30720
#define STAGES  4
#define SMEM_BYTES (STAGES * STAGE_B)     // 122880

template <int KEL>
__device__ __forceinline__ void issue_stage(const char* Ab, const char* Bb,
                                            uint32_t sbase, int kc, int s, int tid)
{
    const size_t rs = (size_t)KEL * 2;
    const char* Ak = Ab + (size_t)kc * (GBK * 2);
    const char* Bk = Bb + (size_t)kc * (GBK * 2);
    const uint32_t sA = sbase + s * STAGE_B;
    const uint32_t sB = sA + A_BYTES;
#pragma unroll
    for (int i = 0; i < 6; i++) {           // 1536 16B chunks / 256 threads
        int idx = tid + i * 256;
        int row = idx >> 2;
        int co  = (idx & 3) << 4;
        if (row < GBM)
            cp16(sA + row * ROW_B + co, Ak + (size_t)row * rs + co);
        else
            cp16(sB + (row - GBM) * ROW_B + co, Bk + (size_t)(row - GBM) * rs + co);
    }
    CP_COMMIT();
}

template <int KEL, int SPLIT>
__global__ void __launch_bounds__(256)
gemm_mma(const __half* __restrict__ A,   // [M, KEL]
         const __half* __restrict__ Bt,  // [Ncols, KEL]
         const float* __restrict__ bias0,
         const float* __restrict__ bias1,
         float* __restrict__ C0, float* __restrict__ C1)
{
    constexpr int NKC = KEL / GBK;
    extern __shared__ char smem[];
    const int tid = threadIdx.x, lane = tid & 31, wid = tid >> 5;
    const int wm = wid & 1;        // 0..1 -> M offset wm*64
    const int wn = wid >> 1;       // 0..3 -> N offset wn*64
    const int m0 = blockIdx.y * GBM;
    const int n0 = blockIdx.x * GBN;
    const uint32_t sb = smem_u32(smem);

    const char* Ab = (const char*)A + (size_t)m0 * KEL * 2;
    const char* Bb = (const char*)Bt + (size_t)n0 * KEL * 2;

    float acc[4][8][4];
#pragma unroll
    for (int i = 0; i < 4; i++)
#pragma unroll
        for (int j = 0; j < 8; j++)
#pragma unroll
            for (int q = 0; q < 4; q++) acc[i][j][q] = 0.f;

    issue_stage<KEL>(Ab, Bb, sb, 0, 0, tid);
    issue_stage<KEL>(Ab, Bb, sb, 1, 1, tid);
    issue_stage<KEL>(Ab, Bb, sb, 2, 2, tid);

    const uint32_t aoff = (uint32_t)((wm * 64 + (lane & 15)) * ROW_B
                                     + (lane >> 4) * 16);
    const uint32_t boff = (uint32_t)A_BYTES
                        + (uint32_t)((wn * 64 + ((lane >> 4) & 1) * 8 + (lane & 7)) * ROW_B
                                     + ((lane >> 3) & 1) * 16);

    for (int kc = 0; kc < NKC; kc++) {
        CP_WAIT(2);
        __syncthreads();
        if (kc + 3 < NKC) issue_stage<KEL>(Ab, Bb, sb, kc + 3, (kc + 3) & 3, tid);
        else              CP_COMMIT();

        const uint32_t sA = sb + (kc & 3) * STAGE_B;
#pragma unroll
        for (int kp = 0; kp < 2; kp++) {
            uint32_t af[4][4], bf[4][4];
#pragma unroll
            for (int mi = 0; mi < 4; mi++)
                ldm4(af[mi], sA + aoff + mi * 16 * ROW_B + kp * 32);
#pragma unroll
            for (int j = 0; j < 4; j++)
                ldm4(bf[j], sA + boff + j * 16 * ROW_B + kp * 32);
#pragma unroll
            for (int mi = 0; mi < 4; mi++)
#pragma unroll
                for (int nj = 0; nj < 8; nj++)
                    mma_f16(acc[mi][nj], af[mi], &bf[nj >> 1][(nj & 1) * 2]);
        }
    }

    // Epilogue
    const int gid = lane >> 2, tig = lane & 3;
    float* C = C0;
    const float* bias = bias0;
    int stride = SPLIT ? (3 * DD) : DD;
    int ncol = n0;
    bool sig = false;
    if (SPLIT) {
        if (n0 >= 3 * DD) {           // gate region
            C = C1; bias = bias1; stride = DD; ncol = n0 - 3 * DD; sig = true;
        }
    }
#pragma unroll
    for (int mi = 0; mi < 4; mi++) {
        const int r0 = m0 + wm * 64 + mi * 16 + gid;
#pragma unroll
        for (int nj = 0; nj < 8; nj++) {
            const int col = ncol + wn * 64 + nj * 8 + tig * 2;
            const float b0 = bias[col], b1 = bias[col + 1];
            float2 v;
            v.x = acc[mi][nj][0] + b0;
            v.y = acc[mi][nj][1] + b1;
            if (sig) {
                v.x = 1.f / (1.f + __expf(-v.x));
                v.y = 1.f / (1.f + __expf(-v.y));
            }
            *(float2*)(C + (size_t)r0 * stride + col) = v;
            v.x = acc[mi][nj][2] + b0;
            v.y = acc[mi][nj][3] + b1;
            if (sig) {
                v.x = 1.f / (1.f + __expf(-v.x));
                v.y = 1.f / (1.f + __expf(-v.y));
            }
            *(float2*)(C + (size_t)(r0 + 8) * stride + col) = v;
        }
    }
}

// ---------------------------------------------------------------------------
// 24-tap dilated attention + gate multiply; writes 3-term split fp16 gs.
// One warp per (n, h); each lane owns dims 2*lane, 2*lane+1.
// ---------------------------------------------------------------------------
__global__ void attn_kernel(const float* __restrict__ qkv,
                            const float* __restrict__ gate,
                            const float* __restrict__ pos_bias,
                            __half* __restrict__ gs)
{
    const int gw   = (blockIdx.x * blockDim.x + threadIdx.x) >> 5;
    const int lane = threadIdx.x & 31;
    const int n = gw >> 4;
    const int h = gw & 15;
    if (n >= NN) return;

    const float scale = 0.125f;
    const size_t rowQ = (size_t)n * (3 * DD) + h * HDD;
    const float2 q = *(const float2*)(qkv + rowQ + 2 * lane);

    float sc[NOFF];
#pragma unroll
    for (int o = 0; o < NOFF; o++) {
        const int src = n - c_off[o];
        float s = 0.f;
        if (src >= 0) {
            const float2 k = *(const float2*)(qkv + (size_t)src * (3 * DD) + DD
                                              + h * HDD + 2 * lane);
            s = q.x * k.x + q.y * k.y;
        }
#pragma unroll
        for (int d = 16; d > 0; d >>= 1)
            s += __shfl_xor_sync(0xffffffffu, s, d);
        sc[o] = s * scale + pos_bias[o * HH + h];
    }

    float mx = sc[0];
#pragma unroll
    for (int o = 1; o < NOFF; o++) mx = fmaxf(mx, sc[o]);
    float den = 0.f;
#pragma unroll
    for (int o = 0; o < NOFF; o++) { sc[o] = __expf(sc[o] - mx); den += sc[o]; }
    const float inv = 1.f / den;

    float ax = 0.f, ay = 0.f;
#pragma unroll
    for (int o = 0; o < NOFF; o++) {
        const int src = n - c_off[o];
        if (src >= 0) {
            const float2 v = *(const float2*)(qkv + (size_t)src * (3 * DD) + 2 * DD
                                              + h * HDD + 2 * lane);
            const float w = sc[o] * inv;
            ax += w * v.x;
            ay += w * v.y;
        }
    }

    const int kcol = h * HDD + 2 * lane;
    const size_t oidx = (size_t)n * DD + kcol;
    const float2 g = *(const float2*)(gate + oidx);
    const float v0 = ax * g.x;
    const float v1 = ay * g.y;

    // 3-term split write: [hi | lo | hi]
    __half h0 = __float2half_rn(v0);
    __half h1 = __float2half_rn(v1);
    __half l0 = __float2half_rn(v0 - __half2float(h0));
    __half l1 = __float2half_rn(v1 - __half2float(h1));
    const size_t b = (size_t)n * KB + kcol;
    __half2 hp; hp.x = h0; hp.y = h1;
    __half2 lp; lp.x = l0; lp.y = l1;
    *(__half2*)(gs + b)        = hp;
    *(__half2*)(gs + b + 1024) = lp;
    *(__half2*)(gs + b + 2048) = hp;
}

// ---------------------------------------------------------------------------
extern "C" void kernel_launch(void* const* d_in, const int* in_sizes, int n_in,
                              void* d_out, int out_size)
{
    const float* x     = (const float*)d_in[0];
    const float* Wqkv  = (const float*)d_in[1];
    const float* bqkv  = (const float*)d_in[2];
    const float* Wout  = (const float*)d_in[3];
    const float* bout  = (const float*)d_in[4];
    const float* Wgate = (const float*)d_in[5];
    const float* bgate = (const float*)d_in[6];
    const float* pbias = (const float*)d_in[7];
    float* out = (float*)d_out;

    __half *xs, *gs, *W1t, *Wot;
    float *qkv, *gate;
    cudaGetSymbolAddress((void**)&xs,   g_xs);
    cudaGetSymbolAddress((void**)&gs,   g_gs);
    cudaGetSymbolAddress((void**)&W1t,  g_W1t);
    cudaGetSymbolAddress((void**)&Wot,  g_Wot);
    cudaGetSymbolAddress((void**)&qkv,  g_qkv);
    cudaGetSymbolAddress((void**)&gate, g_gate);

    cudaFuncSetAttribute(gemm_mma<KA,1>, cudaFuncAttributeMaxDynamicSharedMemorySize, SMEM_BYTES);
    cudaFuncSetAttribute(gemm_mma<KB,0>, cudaFuncAttributeMaxDynamicSharedMemorySize, SMEM_BYTES);

    // Conversions
    conv_x_kernel<<<(NN * DD) / 256, 256>>>(x, xs);
    conv_w2_kernel<<<dim3(3 * DD / 32, DD / 32), dim3(32, 8)>>>(Wqkv, W1t, 3 * DD, 0);
    conv_w2_kernel<<<dim3(DD / 32, DD / 32), dim3(32, 8)>>>(Wgate, W1t, DD, 3 * DD);
    conv_w3_kernel<<<dim3(DD / 32, DD / 32), dim3(32, 8)>>>(Wout, Wot);

    // 1) fused: [qkv | gate] = x @ [Wqkv | Wgate] (+sigmoid on gate region)
    gemm_mma<KA,1><<<dim3(4 * DD / GBN, NN / GBM), 256, SMEM_BYTES>>>(
        xs, W1t, bqkv, bgate, qkv, gate);
    // 2) attention + gate multiply -> gs (3-term split fp16)
    attn_kernel<<<(NN * HH * 32) / 256, 256>>>(qkv, gate, pbias, gs);
    // 3) out = gated @ Wout + bout
    gemm_mma<KB,0><<<dim3(DD / GBN, NN / GBM), 256, SMEM_BYTES>>>(
        gs, Wot, bout, bout, out, out);
}

// round 12
// speedup vs baseline: 2.6059x; 1.1616x over previous
#include <cuda_runtime.h>
#include <cuda_fp16.h>
#include <math.h>
#include <stdint.h>

// Problem constants
#define NN   4096
#define DD   1024
#define HH   16
#define HDD  64
#define NOFF 24
#define KA   2048           // 2-term split-K: [Ah | Al] x [Bh | Bh]  (err ~2^-11)

// ---------------------------------------------------------------------------
// Scratch (__device__ globals; no cudaMalloc allowed)
// ---------------------------------------------------------------------------
__device__ __align__(16) __half g_xs  [(size_t)NN * KA];        // x split [hi|lo]
__device__ __align__(16) __half g_gs  [(size_t)NN * KA];        // gated split [hi|lo]
__device__ __align__(16) __half g_W1t [(size_t)(3*DD) * KA];    // WqkvT  [hi|hi]
__device__ __align__(16) __half g_Wgt [(size_t)DD * DD];        // WgateT [hi] single-plane
__device__ __align__(16) __half g_Wot [(size_t)DD * KA];        // WoutT  [hi|hi]
__device__ __align__(16) float g_qkv [(size_t)NN * 3 * DD];
__device__ __align__(16) float g_gate[(size_t)NN * DD];

__constant__ int c_off[NOFF] = {0,1,2,3,4,6,8,12,16,24,32,48,64,96,128,
                                192,256,384,512,768,1024,1536,2048,3072};

// ---------------------------------------------------------------------------
// PTX helpers (sm_80-level only: compute_103 family target accepts these)
// ---------------------------------------------------------------------------
__device__ __forceinline__ uint32_t smem_u32(const void* p) {
    uint32_t a;
    asm("{ .reg .u64 t; cvta.to.shared.u64 t, %1; cvt.u32.u64 %0, t; }"
        : "=r"(a) : "l"(p));
    return a;
}
__device__ __forceinline__ void cp16(uint32_t s, const void* g) {
    asm volatile("cp.async.cg.shared.global [%0], [%1], 16;" :: "r"(s), "l"(g));
}
#define CP_COMMIT()  asm volatile("cp.async.commit_group;" ::: "memory")
#define CP_WAIT(n)   asm volatile("cp.async.wait_group %0;" :: "n"(n) : "memory")

__device__ __forceinline__ void ldm4(uint32_t* r, uint32_t addr) {
    asm volatile("ldmatrix.sync.aligned.m8n8.x4.shared.b16 {%0,%1,%2,%3}, [%4];"
                 : "=r"(r[0]), "=r"(r[1]), "=r"(r[2]), "=r"(r[3]) : "r"(addr));
}
__device__ __forceinline__ void mma_f16(float* d, const uint32_t* a, const uint32_t* b) {
    asm volatile(
        "mma.sync.aligned.m16n8k16.row.col.f32.f16.f16.f32 "
        "{%0,%1,%2,%3}, {%4,%5,%6,%7}, {%8,%9}, {%0,%1,%2,%3};"
        : "+f"(d[0]), "+f"(d[1]), "+f"(d[2]), "+f"(d[3])
        : "r"(a[0]), "r"(a[1]), "r"(a[2]), "r"(a[3]), "r"(b[0]), "r"(b[1]));
}

// ---------------------------------------------------------------------------
// Conversions
// ---------------------------------------------------------------------------
// x [4096,1024] f32 -> [hi | lo] fp16, row stride 2048
__global__ void conv_x_kernel(const float* __restrict__ X, __half* __restrict__ Y)
{
    int idx = blockIdx.x * blockDim.x + threadIdx.x;
    int m = idx >> 10, k = idx & 1023;
    float v = X[idx];
    __half hi = __float2half_rn(v);
    __half lo = __float2half_rn(v - __half2float(hi));
    size_t b = (size_t)m * KA;
    Y[b + k] = hi;
    Y[b + 1024 + k] = lo;
}

// W [1024, Ncols] f32 -> Wt rows [row_off + n] x 2048, blocks [hi | hi]
__global__ void conv_w2_kernel(const float* __restrict__ W,
                               __half* __restrict__ Wt, int Ncols, int row_off)
{
    __shared__ float t[32][33];
    const int tx = threadIdx.x, ty = threadIdx.y;
    const int n0 = blockIdx.x * 32, k0 = blockIdx.y * 32;
#pragma unroll
    for (int i = 0; i < 4; i++)
        t[ty + 8 * i][tx] = W[(size_t)(k0 + ty + 8 * i) * Ncols + n0 + tx];
    __syncthreads();
#pragma unroll
    for (int i = 0; i < 4; i++) {
        int n = n0 + ty + 8 * i;
        int k = k0 + tx;
        __half hi = __float2half_rn(t[tx][ty + 8 * i]);
        size_t b = (size_t)(row_off + n) * KA;
        Wt[b + k] = hi;
        Wt[b + 1024 + k] = hi;
    }
}

// Wgate [1024, 1024] f32 -> WgT [n][1024] single-plane fp16
__global__ void conv_wg_kernel(const float* __restrict__ W, __half* __restrict__ Wt)
{
    __shared__ float t[32][33];
    const int tx = threadIdx.x, ty = threadIdx.y;
    const int n0 = blockIdx.x * 32, k0 = blockIdx.y * 32;
#pragma unroll
    for (int i = 0; i < 4; i++)
        t[ty + 8 * i][tx] = W[(size_t)(k0 + ty + 8 * i) * DD + n0 + tx];
    __syncthreads();
#pragma unroll
    for (int i = 0; i < 4; i++) {
        int n = n0 + ty + 8 * i;
        int k = k0 + tx;
        Wt[(size_t)n * DD + k] = __float2half_rn(t[tx][ty + 8 * i]);
    }
}

// ---------------------------------------------------------------------------
// fp16 mma.sync GEMM: C[M, ldc-region] = A'[M, KEXT] @ Bt'[Nc, KEXT]^T + bias
// CTA tile 128x256, BK=32, 256 threads (2x4 warps, warp tile 64x64),
// 4-stage cp.async pipeline, padded 80B smem rows (conflict-free ldmatrix).
// LDA/LDB = row strides (elements) -> permits reading the hi plane only.
// ---------------------------------------------------------------------------
#define GBM     128
#define GBN     256
#define GBK     32
#define ROW_B   80                    // 32 fp16 (64B) + 16B pad
#define A_BYTES (GBM * ROW_B)         // 10240
#define STAGE_B (A_BYTES + GBN * ROW_B)   // 30720
#define STAGES  4
#define SMEM_BYTES (STAGES * STAGE_B)     // 122880

template <int LDA, int LDB>
__device__ __forceinline__ void issue_stage(const char* Ab, const char* Bb,
                                            uint32_t sbase, int kc, int s, int tid)
{
    const char* Ak = Ab + (size_t)kc * (GBK * 2);
    const char* Bk = Bb + (size_t)kc * (GBK * 2);
    const uint32_t sA = sbase + s * STAGE_B;
    const uint32_t sB = sA + A_BYTES;
#pragma unroll
    for (int i = 0; i < 6; i++) {           // 1536 16B chunks / 256 threads
        int idx = tid + i * 256;
        int row = idx >> 2;
        int co  = (idx & 3) << 4;
        if (row < GBM)
            cp16(sA + row * ROW_B + co, Ak + (size_t)row * (LDA * 2) + co);
        else
            cp16(sB + (row - GBM) * ROW_B + co, Bk + (size_t)(row - GBM) * (LDB * 2) + co);
    }
    CP_COMMIT();
}

template <int KEXT, int LDA, int LDB, int ACT>
__global__ void __launch_bounds__(256)
gemm_mma(const __half* __restrict__ A,   // [M, LDA], K extent KEXT
         const __half* __restrict__ Bt,  // [Ncols, LDB], K extent KEXT
         const float* __restrict__ bias,
         float* __restrict__ C, int ldc)
{
    constexpr int NKC = KEXT / GBK;
    extern __shared__ char smem[];
    const int tid = threadIdx.x, lane = tid & 31, wid = tid >> 5;
    const int wm = wid & 1;        // 0..1 -> M offset wm*64
    const int wn = wid >> 1;       // 0..3 -> N offset wn*64
    const int m0 = blockIdx.y * GBM;
    const int n0 = blockIdx.x * GBN;
    const uint32_t sb = smem_u32(smem);

    const char* Ab = (const char*)A + (size_t)m0 * LDA * 2;
    const char* Bb = (const char*)Bt + (size_t)n0 * LDB * 2;

    float acc[4][8][4];
#pragma unroll
    for (int i = 0; i < 4; i++)
#pragma unroll
        for (int j = 0; j < 8; j++)
#pragma unroll
            for (int q = 0; q < 4; q++) acc[i][j][q] = 0.f;

    issue_stage<LDA, LDB>(Ab, Bb, sb, 0, 0, tid);
    issue_stage<LDA, LDB>(Ab, Bb, sb, 1, 1, tid);
    issue_stage<LDA, LDB>(Ab, Bb, sb, 2, 2, tid);

    const uint32_t aoff = (uint32_t)((wm * 64 + (lane & 15)) * ROW_B
                                     + (lane >> 4) * 16);
    const uint32_t boff = (uint32_t)A_BYTES
                        + (uint32_t)((wn * 64 + ((lane >> 4) & 1) * 8 + (lane & 7)) * ROW_B
                                     + ((lane >> 3) & 1) * 16);

    for (int kc = 0; kc < NKC; kc++) {
        CP_WAIT(2);
        __syncthreads();
        if (kc + 3 < NKC) issue_stage<LDA, LDB>(Ab, Bb, sb, kc + 3, (kc + 3) & 3, tid);
        else              CP_COMMIT();

        const uint32_t sA = sb + (kc & 3) * STAGE_B;
#pragma unroll
        for (int kp = 0; kp < 2; kp++) {
            uint32_t af[4][4], bf[4][4];
#pragma unroll
            for (int mi = 0; mi < 4; mi++)
                ldm4(af[mi], sA + aoff + mi * 16 * ROW_B + kp * 32);
#pragma unroll
            for (int j = 0; j < 4; j++)
                ldm4(bf[j], sA + boff + j * 16 * ROW_B + kp * 32);
#pragma unroll
            for (int mi = 0; mi < 4; mi++)
#pragma unroll
                for (int nj = 0; nj < 8; nj++)
                    mma_f16(acc[mi][nj], af[mi], &bf[nj >> 1][(nj & 1) * 2]);
        }
    }

    // Epilogue
    const int gid = lane >> 2, tig = lane & 3;
#pragma unroll
    for (int mi = 0; mi < 4; mi++) {
        const int r0 = m0 + wm * 64 + mi * 16 + gid;
#pragma unroll
        for (int nj = 0; nj < 8; nj++) {
            const int col = n0 + wn * 64 + nj * 8 + tig * 2;
            const float b0 = bias[col], b1 = bias[col + 1];
            float2 v;
            v.x = acc[mi][nj][0] + b0;
            v.y = acc[mi][nj][1] + b1;
            if (ACT == 1) {
                v.x = 1.f / (1.f + __expf(-v.x));
                v.y = 1.f / (1.f + __expf(-v.y));
            }
            *(float2*)(C + (size_t)r0 * ldc + col) = v;
            v.x = acc[mi][nj][2] + b0;
            v.y = acc[mi][nj][3] + b1;
            if (ACT == 1) {
                v.x = 1.f / (1.f + __expf(-v.x));
                v.y = 1.f / (1.f + __expf(-v.y));
            }
            *(float2*)(C + (size_t)(r0 + 8) * ldc + col) = v;
        }
    }
}

// ---------------------------------------------------------------------------
// 24-tap dilated attention + gate multiply; writes 2-term split fp16 gs.
// One warp per (n, h); each lane owns dims 2*lane, 2*lane+1.
// ---------------------------------------------------------------------------
__global__ void attn_kernel(const float* __restrict__ qkv,
                            const float* __restrict__ gate,
                            const float* __restrict__ pos_bias,
                            __half* __restrict__ gs)
{
    const int gw   = (blockIdx.x * blockDim.x + threadIdx.x) >> 5;
    const int lane = threadIdx.x & 31;
    const int n = gw >> 4;
    const int h = gw & 15;
    if (n >= NN) return;

    const float scale = 0.125f;
    const size_t rowQ = (size_t)n * (3 * DD) + h * HDD;
    const float2 q = *(const float2*)(qkv + rowQ + 2 * lane);

    float sc[NOFF];
#pragma unroll
    for (int o = 0; o < NOFF; o++) {
        const int src = n - c_off[o];
        float s = 0.f;
        if (src >= 0) {
            const float2 k = *(const float2*)(qkv + (size_t)src * (3 * DD) + DD
                                              + h * HDD + 2 * lane);
            s = q.x * k.x + q.y * k.y;
        }
#pragma unroll
        for (int d = 16; d > 0; d >>= 1)
            s += __shfl_xor_sync(0xffffffffu, s, d);
        sc[o] = s * scale + pos_bias[o * HH + h];
    }

    float mx = sc[0];
#pragma unroll
    for (int o = 1; o < NOFF; o++) mx = fmaxf(mx, sc[o]);
    float den = 0.f;
#pragma unroll
    for (int o = 0; o < NOFF; o++) { sc[o] = __expf(sc[o] - mx); den += sc[o]; }
    const float inv = 1.f / den;

    float ax = 0.f, ay = 0.f;
#pragma unroll
    for (int o = 0; o < NOFF; o++) {
        const int src = n - c_off[o];
        if (src >= 0) {
            const float2 v = *(const float2*)(qkv + (size_t)src * (3 * DD) + 2 * DD
                                              + h * HDD + 2 * lane);
            const float w = sc[o] * inv;
            ax += w * v.x;
            ay += w * v.y;
        }
    }

    const int kcol = h * HDD + 2 * lane;
    const size_t oidx = (size_t)n * DD + kcol;
    const float2 g = *(const float2*)(gate + oidx);
    const float v0 = ax * g.x;
    const float v1 = ay * g.y;

    // 2-term split write: [hi | lo]
    __half h0 = __float2half_rn(v0);
    __half h1 = __float2half_rn(v1);
    __half l0 = __float2half_rn(v0 - __half2float(h0));
    __half l1 = __float2half_rn(v1 - __half2float(h1));
    const size_t b = (size_t)n * KA + kcol;
    __half2 hp; hp.x = h0; hp.y = h1;
    __half2 lp; lp.x = l0; lp.y = l1;
    *(__half2*)(gs + b)        = hp;
    *(__half2*)(gs + b + 1024) = lp;
}

// ---------------------------------------------------------------------------
extern "C" void kernel_launch(void* const* d_in, const int* in_sizes, int n_in,
                              void* d_out, int out_size)
{
    const float* x     = (const float*)d_in[0];
    const float* Wqkv  = (const float*)d_in[1];
    const float* bqkv  = (const float*)d_in[2];
    const float* Wout  = (const float*)d_in[3];
    const float* bout  = (const float*)d_in[4];
    const float* Wgate = (const float*)d_in[5];
    const float* bgate = (const float*)d_in[6];
    const float* pbias = (const float*)d_in[7];
    float* out = (float*)d_out;

    __half *xs, *gs, *W1t, *Wgt, *Wot;
    float *qkv, *gate;
    cudaGetSymbolAddress((void**)&xs,   g_xs);
    cudaGetSymbolAddress((void**)&gs,   g_gs);
    cudaGetSymbolAddress((void**)&W1t,  g_W1t);
    cudaGetSymbolAddress((void**)&Wgt,  g_Wgt);
    cudaGetSymbolAddress((void**)&Wot,  g_Wot);
    cudaGetSymbolAddress((void**)&qkv,  g_qkv);
    cudaGetSymbolAddress((void**)&gate, g_gate);

    cudaFuncSetAttribute((const void*)gemm_mma<2048,2048,2048,0>,
                         cudaFuncAttributeMaxDynamicSharedMemorySize, SMEM_BYTES);
    cudaFuncSetAttribute((const void*)gemm_mma<1024,2048,1024,1>,
                         cudaFuncAttributeMaxDynamicSharedMemorySize, SMEM_BYTES);

    // Conversions
    conv_x_kernel<<<(NN * DD) / 256, 256>>>(x, xs);
    conv_w2_kernel<<<dim3(3 * DD / 32, DD / 32), dim3(32, 8)>>>(Wqkv, W1t, 3 * DD, 0);
    conv_wg_kernel<<<dim3(DD / 32, DD / 32), dim3(32, 8)>>>(Wgate, Wgt);
    conv_w2_kernel<<<dim3(DD / 32, DD / 32), dim3(32, 8)>>>(Wout, Wot, DD, 0);

    // 1) qkv = x @ Wqkv + bqkv           (2-term fp16 split, K'=2048)
    gemm_mma<2048,2048,2048,0><<<dim3(3 * DD / GBN, NN / GBM), 256, SMEM_BYTES>>>(
        xs, W1t, bqkv, qkv, 3 * DD);
    // 2) gate = sigmoid(x @ Wgate + bgate)  (single-plane fp16, K=1024;
    //    sigmoid'(~2) ~ 0.1 makes the fp16 error negligible)
    gemm_mma<1024,2048,1024,1><<<dim3(DD / GBN, NN / GBM), 256, SMEM_BYTES>>>(
        xs, Wgt, bgate, gate, DD);
    // 3) attention + gate multiply -> gs (2-term split fp16)
    attn_kernel<<<(NN * HH * 32) / 256, 256>>>(qkv, gate, pbias, gs);
    // 4) out = gated @ Wout + bout       (2-term fp16 split, K'=2048)
    gemm_mma<2048,2048,2048,0><<<dim3(DD / GBN, NN / GBM), 256, SMEM_BYTES>>>(
        gs, Wot, bout, out, DD);
}